// round 7
// baseline (speedup 1.0000x reference)
#include <cuda_runtime.h>
#include <cstdint>

// LatentTexture: quantize-then-bilinear-sample two latent textures.
//   hi: 12 ch, 2048x2048, 8-bit quant (qmax=255)
//   lo:  4 ch,  512x512,  4-bit quant (qmax=15)
// out[b,0:12]=hi, out[b,12:16]=lo. fp32.
//
// R5: spatial counting sort of samples by 32x32-texel tile (Morton-ordered
// 64x64 bin grid = 4096 bins), then gather in sorted order. Warps then touch
// tiny tile footprints -> L1/L2 dedup to the distinct-granule bound and
// DRAM row-buffer locality. 4 threads per sample (one float4 group each);
// output rows are full 64B granules scattered by original index.

#define NSAMP 131072
#define BLK 256
#define NBINS 4096   // 64x64 tiles of 32x32 texels (hi space)

__device__ int      g_hist[NBINS];
__device__ int      g_cursor[NBINS];
__device__ float2   g_sorted_uv[NSAMP];
__device__ int      g_sorted_idx[NSAMP];

// ---------------------------------------------------------------- helpers
__device__ __forceinline__ float qlevel(float x, float qmax) {
    float xc = fminf(fmaxf(x, 0.0f), 1.0f);
    return rintf(__fmul_rn(xc, qmax));
}

__device__ __forceinline__ uint32_t spread6(uint32_t x) {
    // interleave-ready spread of 6 bits (works for up to 8)
    x &= 0xFFu;
    x = (x | (x << 4)) & 0x0F0Fu;
    x = (x | (x << 2)) & 0x3333u;
    x = (x | (x << 1)) & 0x5555u;
    return x;
}

__device__ __forceinline__ int sample_key(float u, float v) {
    // hi-space ix/iy (same arithmetic path as sampling; any consistent key ok)
    float gx = __fadd_rn(__fmul_rn(u, 2.0f), -1.0f);
    float gy = __fadd_rn(__fmul_rn(v, 2.0f), -1.0f);
    float ix = __fmul_rn(__fmul_rn(__fadd_rn(gx, 1.0f), 0.5f), 2047.0f);
    float iy = __fmul_rn(__fmul_rn(__fadd_rn(gy, 1.0f), 0.5f), 2047.0f);
    int tx = min(max((int)floorf(ix), 0), 2047) >> 5;   // 0..63
    int ty = min(max((int)floorf(iy), 0), 2047) >> 5;   // 0..63
    return (int)((spread6((uint32_t)ty) << 1) | spread6((uint32_t)tx));
}

// ---------------------------------------------------------------- sort passes
__global__ void __launch_bounds__(BLK) zero_hist_kernel() {
    int i = blockIdx.x * BLK + threadIdx.x;
    if (i < NBINS) g_hist[i] = 0;
}

__global__ void __launch_bounds__(BLK)
hist_kernel(const float* __restrict__ uv) {
    int i = blockIdx.x * BLK + threadIdx.x;
    float2 p = __ldg(reinterpret_cast<const float2*>(uv) + i);
    atomicAdd(&g_hist[sample_key(p.x, p.y)], 1);
}

__global__ void __launch_bounds__(1024) scan_kernel() {
    __shared__ int sh[1024];
    int tid = threadIdx.x;
    int4 v = reinterpret_cast<const int4*>(g_hist)[tid];
    int s = v.x + v.y + v.z + v.w;
    sh[tid] = s;
    __syncthreads();
    for (int off = 1; off < 1024; off <<= 1) {
        int t = (tid >= off) ? sh[tid - off] : 0;
        __syncthreads();
        sh[tid] += t;
        __syncthreads();
    }
    int excl = sh[tid] - s;
    int4 c;
    c.x = excl;
    c.y = excl + v.x;
    c.z = excl + v.x + v.y;
    c.w = excl + v.x + v.y + v.z;
    reinterpret_cast<int4*>(g_cursor)[tid] = c;
}

__global__ void __launch_bounds__(BLK)
scatter_kernel(const float* __restrict__ uv) {
    int i = blockIdx.x * BLK + threadIdx.x;
    float2 p = __ldg(reinterpret_cast<const float2*>(uv) + i);
    int pos = atomicAdd(&g_cursor[sample_key(p.x, p.y)], 1);
    g_sorted_uv[pos] = p;
    g_sorted_idx[pos] = i;
}

// ---------------------------------------------------------------- gather
// Sample 4 consecutive channel planes of a HWxHW texture at (u,v).
template <int HW>
__device__ __forceinline__ void sample4(const float* __restrict__ tex,
                                        float u, float v,
                                        float qmax, float invq,
                                        float* __restrict__ res) {
    float gx = __fadd_rn(__fmul_rn(u, 2.0f), -1.0f);
    float gy = __fadd_rn(__fmul_rn(v, 2.0f), -1.0f);
    float ix = __fmul_rn(__fmul_rn(__fadd_rn(gx, 1.0f), 0.5f), (float)(HW - 1));
    float iy = __fmul_rn(__fmul_rn(__fadd_rn(gy, 1.0f), 0.5f), (float)(HW - 1));

    float ix0f = floorf(ix);
    float iy0f = floorf(iy);
    float wx = __fadd_rn(ix, -ix0f);
    float wy = __fadd_rn(iy, -iy0f);

    int ix0 = min(max((int)ix0f, 0), HW - 1);
    int iy0 = min(max((int)iy0f, 0), HW - 1);
    int ix1 = min(ix0 + 1, HW - 1);
    int iy1 = min(iy0 + 1, HW - 1);

    float w00 = (1.0f - wy) * (1.0f - wx);
    float w01 = (1.0f - wy) * wx;
    float w10 = wy * (1.0f - wx);
    float w11 = wy * wx;

    size_t r0 = (size_t)iy0 * HW;
    size_t r1 = (size_t)iy1 * HW;
    size_t o00 = r0 + ix0, o01 = r0 + ix1;
    size_t o10 = r1 + ix0, o11 = r1 + ix1;

    const size_t plane = (size_t)HW * HW;

    float t00[4], t01[4], t10[4], t11[4];
#pragma unroll
    for (int c = 0; c < 4; ++c) {
        const float* p = tex + (size_t)c * plane;
        t00[c] = __ldg(p + o00);
        t01[c] = __ldg(p + o01);
        t10[c] = __ldg(p + o10);
        t11[c] = __ldg(p + o11);
    }
#pragma unroll
    for (int c = 0; c < 4; ++c) {
        float acc = qlevel(t00[c], qmax) * w00
                  + qlevel(t01[c], qmax) * w01
                  + qlevel(t10[c], qmax) * w10
                  + qlevel(t11[c], qmax) * w11;
        res[c] = acc * invq;
    }
}

__global__ void __launch_bounds__(BLK)
gather_kernel(const float* __restrict__ hi,
              const float* __restrict__ lo,
              float* __restrict__ out) {
    int t = blockIdx.x * BLK + threadIdx.x;
    int s = t >> 2;       // sorted position
    int j = t & 3;        // output float4 group

    float2 p = g_sorted_uv[s];      // 4 lanes read same 8B -> L1 broadcast
    int idx = g_sorted_idx[s];

    float res[4];
    if (j < 3) {
        const size_t plane = (size_t)2048 * 2048;
        sample4<2048>(hi + (size_t)(j * 4) * plane, p.x, p.y,
                      255.0f, 1.0f / 255.0f, res);
    } else {
        sample4<512>(lo, p.x, p.y, 15.0f, 1.0f / 15.0f, res);
    }

    reinterpret_cast<float4*>(out)[(size_t)idx * 4 + j] =
        make_float4(res[0], res[1], res[2], res[3]);
}

// ---------------------------------------------------------------- launch
extern "C" void kernel_launch(void* const* d_in, const int* in_sizes, int n_in,
                              void* d_out, int out_size) {
    const float* uv = (const float*)d_in[0];
    const float* hi = (const float*)d_in[1];
    const float* lo = (const float*)d_in[2];
    float* out = (float*)d_out;

    zero_hist_kernel<<<(NBINS + BLK - 1) / BLK, BLK>>>();
    hist_kernel<<<NSAMP / BLK, BLK>>>(uv);
    scan_kernel<<<1, 1024>>>();
    scatter_kernel<<<NSAMP / BLK, BLK>>>(uv);
    gather_kernel<<<NSAMP * 4 / BLK, BLK>>>(hi, lo, out);
}

// round 9
// speedup vs baseline: 1.1695x; 1.1695x over previous
#include <cuda_runtime.h>
#include <cstdint>

// LatentTexture: quantize-then-bilinear-sample two latent textures.
//   hi: 12 ch, 2048x2048, 8-bit quant (qmax=255)
//   lo:  4 ch,  512x512,  4-bit quant (qmax=15)
// out[b,0:12]=hi, out[b,12:16]=lo. fp32.
//
// R8: counting sort by 16x16-texel Morton tile (16384 bins), heavily
// de-overheaded:
//   - no zero pass (globals are zero-init at load; scan re-zeroes hist)
//   - hist/scatter process 4 samples/thread (MLP on 318-cyc atomics)
//   - fused 16B record (u,v,idx) -> STG.128 / LDG.128
// Gather: 4 threads per sample, sorted order -> warp footprint ~1 bin.

#define NSAMP 131072
#define BLK 256
#define NBINS 16384          // 128x128 tiles of 16x16 hi texels
#define SCAN_T 1024
#define BINS_PER_T (NBINS / SCAN_T)   // 16

__device__ int    g_hist[NBINS];      // zero at module load; scan re-zeroes
__device__ int    g_cursor[NBINS];
__device__ float4 g_sorted[NSAMP];    // (u, v, idx_bits, pad)

// ---------------------------------------------------------------- helpers
__device__ __forceinline__ float qlevel(float x, float qmax) {
    float xc = fminf(fmaxf(x, 0.0f), 1.0f);
    return rintf(__fmul_rn(xc, qmax));
}

__device__ __forceinline__ uint32_t spread8(uint32_t x) {
    x &= 0xFFu;
    x = (x | (x << 4)) & 0x0F0Fu;
    x = (x | (x << 2)) & 0x3333u;
    x = (x | (x << 1)) & 0x5555u;
    return x;
}

__device__ __forceinline__ int sample_key(float u, float v) {
    float gx = __fadd_rn(__fmul_rn(u, 2.0f), -1.0f);
    float gy = __fadd_rn(__fmul_rn(v, 2.0f), -1.0f);
    float ix = __fmul_rn(__fmul_rn(__fadd_rn(gx, 1.0f), 0.5f), 2047.0f);
    float iy = __fmul_rn(__fmul_rn(__fadd_rn(gy, 1.0f), 0.5f), 2047.0f);
    int tx = min(max((int)floorf(ix), 0), 2047) >> 4;   // 0..127
    int ty = min(max((int)floorf(iy), 0), 2047) >> 4;   // 0..127
    return (int)((spread8((uint32_t)ty) << 1) | spread8((uint32_t)tx));
}

// ---------------------------------------------------------------- sort
__global__ void __launch_bounds__(BLK)
hist_kernel(const float* __restrict__ uv) {
    int t = blockIdx.x * BLK + threadIdx.x;          // t in [0, NSAMP/4)
    const float4* uv4 = reinterpret_cast<const float4*>(uv);
    float4 a = __ldg(uv4 + 2 * t);
    float4 b = __ldg(uv4 + 2 * t + 1);
    atomicAdd(&g_hist[sample_key(a.x, a.y)], 1);     // result unused -> RED
    atomicAdd(&g_hist[sample_key(a.z, a.w)], 1);
    atomicAdd(&g_hist[sample_key(b.x, b.y)], 1);
    atomicAdd(&g_hist[sample_key(b.z, b.w)], 1);
}

__global__ void __launch_bounds__(SCAN_T) scan_kernel() {
    __shared__ int sh[SCAN_T];
    int tid = threadIdx.x;

    int loc[BINS_PER_T];
    int tot = 0;
#pragma unroll
    for (int k = 0; k < BINS_PER_T / 4; ++k) {
        int4 v = reinterpret_cast<const int4*>(g_hist)[tid * (BINS_PER_T / 4) + k];
        loc[4 * k + 0] = v.x; loc[4 * k + 1] = v.y;
        loc[4 * k + 2] = v.z; loc[4 * k + 3] = v.w;
        tot += v.x + v.y + v.z + v.w;
    }
    sh[tid] = tot;
    __syncthreads();
    for (int off = 1; off < SCAN_T; off <<= 1) {
        int t = (tid >= off) ? sh[tid - off] : 0;
        __syncthreads();
        sh[tid] += t;
        __syncthreads();
    }
    int run = sh[tid] - tot;   // exclusive offset of this thread's range
#pragma unroll
    for (int k = 0; k < BINS_PER_T / 4; ++k) {
        int4 c;
        c.x = run;              run += loc[4 * k + 0];
        c.y = run;              run += loc[4 * k + 1];
        c.z = run;              run += loc[4 * k + 2];
        c.w = run;              run += loc[4 * k + 3];
        reinterpret_cast<int4*>(g_cursor)[tid * (BINS_PER_T / 4) + k] = c;
        // re-zero hist for the next graph replay
        reinterpret_cast<int4*>(g_hist)[tid * (BINS_PER_T / 4) + k] =
            make_int4(0, 0, 0, 0);
    }
}

__global__ void __launch_bounds__(BLK)
scatter_kernel(const float* __restrict__ uv) {
    int t = blockIdx.x * BLK + threadIdx.x;          // t in [0, NSAMP/4)
    const float4* uv4 = reinterpret_cast<const float4*>(uv);
    float4 a = __ldg(uv4 + 2 * t);
    float4 b = __ldg(uv4 + 2 * t + 1);

    float us[4] = {a.x, a.z, b.x, b.z};
    float vs[4] = {a.y, a.w, b.y, b.w};
    int pos[4];
#pragma unroll
    for (int k = 0; k < 4; ++k)                      // 4 independent atomics
        pos[k] = atomicAdd(&g_cursor[sample_key(us[k], vs[k])], 1);
#pragma unroll
    for (int k = 0; k < 4; ++k) {
        int idx = 4 * t + k;
        g_sorted[pos[k]] =
            make_float4(us[k], vs[k], __int_as_float(idx), 0.0f);
    }
}

// ---------------------------------------------------------------- gather
template <int HW>
__device__ __forceinline__ void sample4(const float* __restrict__ tex,
                                        float u, float v,
                                        float qmax, float invq,
                                        float* __restrict__ res) {
    float gx = __fadd_rn(__fmul_rn(u, 2.0f), -1.0f);
    float gy = __fadd_rn(__fmul_rn(v, 2.0f), -1.0f);
    float ix = __fmul_rn(__fmul_rn(__fadd_rn(gx, 1.0f), 0.5f), (float)(HW - 1));
    float iy = __fmul_rn(__fmul_rn(__fadd_rn(gy, 1.0f), 0.5f), (float)(HW - 1));

    float ix0f = floorf(ix);
    float iy0f = floorf(iy);
    float wx = __fadd_rn(ix, -ix0f);
    float wy = __fadd_rn(iy, -iy0f);

    int ix0 = min(max((int)ix0f, 0), HW - 1);
    int iy0 = min(max((int)iy0f, 0), HW - 1);
    int ix1 = min(ix0 + 1, HW - 1);
    int iy1 = min(iy0 + 1, HW - 1);

    float w00 = (1.0f - wy) * (1.0f - wx);
    float w01 = (1.0f - wy) * wx;
    float w10 = wy * (1.0f - wx);
    float w11 = wy * wx;

    size_t r0 = (size_t)iy0 * HW;
    size_t r1 = (size_t)iy1 * HW;
    size_t o00 = r0 + ix0, o01 = r0 + ix1;
    size_t o10 = r1 + ix0, o11 = r1 + ix1;

    const size_t plane = (size_t)HW * HW;

    float t00[4], t01[4], t10[4], t11[4];
#pragma unroll
    for (int c = 0; c < 4; ++c) {
        const float* p = tex + (size_t)c * plane;
        t00[c] = __ldg(p + o00);
        t01[c] = __ldg(p + o01);
        t10[c] = __ldg(p + o10);
        t11[c] = __ldg(p + o11);
    }
#pragma unroll
    for (int c = 0; c < 4; ++c) {
        float acc = qlevel(t00[c], qmax) * w00
                  + qlevel(t01[c], qmax) * w01
                  + qlevel(t10[c], qmax) * w10
                  + qlevel(t11[c], qmax) * w11;
        res[c] = acc * invq;
    }
}

__global__ void __launch_bounds__(BLK)
gather_kernel(const float* __restrict__ hi,
              const float* __restrict__ lo,
              float* __restrict__ out) {
    int t = blockIdx.x * BLK + threadIdx.x;
    int s = t >> 2;       // sorted position
    int j = t & 3;        // output float4 group

    float4 rec = __ldg(reinterpret_cast<const float4*>(g_sorted) + s);
    int idx = __float_as_int(rec.z);

    float res[4];
    if (j < 3) {
        const size_t plane = (size_t)2048 * 2048;
        sample4<2048>(hi + (size_t)(j * 4) * plane, rec.x, rec.y,
                      255.0f, 1.0f / 255.0f, res);
    } else {
        sample4<512>(lo, rec.x, rec.y, 15.0f, 1.0f / 15.0f, res);
    }

    reinterpret_cast<float4*>(out)[(size_t)idx * 4 + j] =
        make_float4(res[0], res[1], res[2], res[3]);
}

// ---------------------------------------------------------------- launch
extern "C" void kernel_launch(void* const* d_in, const int* in_sizes, int n_in,
                              void* d_out, int out_size) {
    const float* uv = (const float*)d_in[0];
    const float* hi = (const float*)d_in[1];
    const float* lo = (const float*)d_in[2];
    float* out = (float*)d_out;

    hist_kernel<<<NSAMP / 4 / BLK, BLK>>>(uv);
    scan_kernel<<<1, SCAN_T>>>();
    scatter_kernel<<<NSAMP / 4 / BLK, BLK>>>(uv);
    gather_kernel<<<NSAMP * 4 / BLK, BLK>>>(hi, lo, out);
}